// round 1
// baseline (speedup 1.0000x reference)
#include <cuda_runtime.h>
#include <cuda_bf16.h>
#include <math.h>

#define N_NODES 50000
#define F_IN    2048
#define POOLD   1024

// ---------------- scratch (static device globals; no allocations) -------------
__device__ float g_h  [(size_t)N_NODES * 1024];  // pooled+LN
__device__ float g_h0 [(size_t)N_NODES * 512];
__device__ float g_h1 [(size_t)N_NODES * 128];
__device__ float g_h2 [(size_t)N_NODES * 64];
__device__ float g_xw1[(size_t)N_NODES * 32];
__device__ float g_ac1[(size_t)N_NODES * 32];    // gcn1 accumulator / activated
__device__ float g_xw2[(size_t)N_NODES * 16];
__device__ float g_ac2[(size_t)N_NODES * 16];    // gcn2 accumulator (z before bias)
__device__ float g_dinv[N_NODES];                 // deg -> rsqrt(deg)

__device__ __forceinline__ float elu1(float v) { return v > 0.f ? v : expm1f(v); }

// ---------------- degree ------------------------------------------------------
__global__ void deg_init_kernel(float* deg) {
    int i = blockIdx.x * blockDim.x + threadIdx.x;
    if (i < N_NODES) deg[i] = 1.0f;  // self loop
}
__global__ void deg_accum_kernel(const int* __restrict__ dst, float* deg, int E) {
    int e = blockIdx.x * blockDim.x + threadIdx.x;
    if (e < E) atomicAdd(&deg[dst[e]], 1.0f);
}
__global__ void deg_final_kernel(float* deg) {
    int i = blockIdx.x * blockDim.x + threadIdx.x;
    if (i < N_NODES) deg[i] = rsqrtf(deg[i]);   // deg >= 1
}

// ---------------- maxpool(2) + layernorm --------------------------------------
__global__ void pool_ln_kernel(const float* __restrict__ x,
                               const float* __restrict__ g,
                               const float* __restrict__ b,
                               float* __restrict__ h) {
    int n = blockIdx.x;
    int t = threadIdx.x;  // 256
    const float2* xr = (const float2*)(x + (size_t)n * F_IN);
    float m[4];
    float sum = 0.f, sumsq = 0.f;
#pragma unroll
    for (int jj = 0; jj < 4; jj++) {
        int j = jj * 256 + t;
        float2 v = xr[j];
        float mm = fmaxf(v.x, v.y);
        m[jj] = mm;
        sum += mm;
        sumsq += mm * mm;
    }
    __shared__ float ssum[8], ssq[8];
#pragma unroll
    for (int off = 16; off > 0; off >>= 1) {
        sum   += __shfl_down_sync(0xffffffffu, sum, off);
        sumsq += __shfl_down_sync(0xffffffffu, sumsq, off);
    }
    int w = t >> 5, l = t & 31;
    if (l == 0) { ssum[w] = sum; ssq[w] = sumsq; }
    __syncthreads();
    __shared__ float s_mu, s_rstd;
    if (t == 0) {
        float S = 0.f, Q = 0.f;
#pragma unroll
        for (int i = 0; i < 8; i++) { S += ssum[i]; Q += ssq[i]; }
        float mu = S * (1.0f / POOLD);
        float var = Q * (1.0f / POOLD) - mu * mu;
        s_mu = mu;
        s_rstd = rsqrtf(var + 1e-5f);
    }
    __syncthreads();
    float mu = s_mu, rstd = s_rstd;
    float* hr = h + (size_t)n * POOLD;
#pragma unroll
    for (int jj = 0; jj < 4; jj++) {
        int j = jj * 256 + t;
        hr[j] = (m[jj] - mu) * rstd * g[j] + b[j];
    }
}

// ---------------- tiled SGEMM: C = act(A[MxK] @ B[KxN] + bias) -----------------
#define BM 128
#define BN 64
#define BK 16
#define TM 8
#define TN 4

__global__ __launch_bounds__(256) void sgemm_bias_act(
    const float* __restrict__ A, const float* __restrict__ B,
    const float* __restrict__ bias, float* __restrict__ C,
    int M, int N, int K, int do_elu) {
    __shared__ float As[BK][BM + 4];
    __shared__ float Bs[BK][BN];
    int tid = threadIdx.x;             // 256
    int tx = tid & 15, ty = tid >> 4;  // 16x16 thread grid
    int rowBase = blockIdx.x * BM;
    int colBase = blockIdx.y * BN;

    float acc[TM][TN];
#pragma unroll
    for (int i = 0; i < TM; i++)
#pragma unroll
        for (int j = 0; j < TN; j++) acc[i][j] = 0.f;

    int ar = tid >> 2;          // 0..63
    int ac = (tid & 3) * 4;     // 0,4,8,12
    int br = tid >> 4;          // 0..15
    int bc = (tid & 15) * 4;    // 0..60

    for (int k0 = 0; k0 < K; k0 += BK) {
#pragma unroll
        for (int gidx = 0; gidx < 2; gidx++) {
            int r = ar + gidx * 64;
            int grow = rowBase + r;
            float4 v = make_float4(0.f, 0.f, 0.f, 0.f);
            if (grow < M) v = *(const float4*)&A[(size_t)grow * K + k0 + ac];
            As[ac + 0][r] = v.x; As[ac + 1][r] = v.y;
            As[ac + 2][r] = v.z; As[ac + 3][r] = v.w;
        }
        {
            float4 v = *(const float4*)&B[(size_t)(k0 + br) * N + colBase + bc];
            Bs[br][bc + 0] = v.x; Bs[br][bc + 1] = v.y;
            Bs[br][bc + 2] = v.z; Bs[br][bc + 3] = v.w;
        }
        __syncthreads();
#pragma unroll
        for (int k = 0; k < BK; k++) {
            float ra[TM], rb[TN];
#pragma unroll
            for (int i = 0; i < TM; i++) ra[i] = As[k][ty * TM + i];
#pragma unroll
            for (int j = 0; j < TN; j++) rb[j] = Bs[k][tx * TN + j];
#pragma unroll
            for (int i = 0; i < TM; i++)
#pragma unroll
                for (int j = 0; j < TN; j++) acc[i][j] += ra[i] * rb[j];
        }
        __syncthreads();
    }
#pragma unroll
    for (int i = 0; i < TM; i++) {
        int grow = rowBase + ty * TM + i;
        if (grow >= M) continue;
#pragma unroll
        for (int j = 0; j < TN; j++) {
            int gcol = colBase + tx * TN + j;
            float v = acc[i][j] + bias[gcol];
            if (do_elu) v = elu1(v);
            C[(size_t)grow * N + gcol] = v;
        }
    }
}

// ---------------- GCN1: xw = h2 @ c1w (64->32), + self-loop init ----------------
__global__ __launch_bounds__(256) void gcn_xw1_kernel(
    const float* __restrict__ h2, const float* __restrict__ W,  // 64x32
    const float* __restrict__ dinv,
    float* __restrict__ xw, float* __restrict__ outbuf) {
    __shared__ float sW[64 * 32];
    int tid = threadIdx.x;
    for (int i = tid; i < 64 * 32; i += 256) sW[i] = W[i];
    __syncthreads();
    int warp = tid >> 5, lane = tid & 31;
    int n = blockIdx.x * 8 + warp;
    if (n >= N_NODES) return;
    const float* row = h2 + (size_t)n * 64;
    float r0 = row[lane], r1 = row[lane + 32];
    float accv = 0.f;
#pragma unroll
    for (int k = 0; k < 32; k++) {
        float a = __shfl_sync(0xffffffffu, r0, k);
        accv += a * sW[k * 32 + lane];
    }
#pragma unroll
    for (int k = 0; k < 32; k++) {
        float a = __shfl_sync(0xffffffffu, r1, k);
        accv += a * sW[(k + 32) * 32 + lane];
    }
    float di = dinv[n];
    xw[(size_t)n * 32 + lane] = accv;
    outbuf[(size_t)n * 32 + lane] = accv * di * di;
}

// scatter: out[dst] += xw[src]*dinv[src]*dinv[dst], 32 channels, thread per (e,c)
__global__ void gcn_scatter32_kernel(const int* __restrict__ src,
                                     const int* __restrict__ dst,
                                     const float* __restrict__ dinv,
                                     const float* __restrict__ xw,
                                     float* __restrict__ outbuf, int E) {
    int idx = blockIdx.x * blockDim.x + threadIdx.x;
    int e = idx >> 5, c = idx & 31;
    if (e >= E) return;
    int s = src[e], d = dst[e];
    float w = dinv[s] * dinv[d];
    atomicAdd(&outbuf[(size_t)d * 32 + c], xw[(size_t)s * 32 + c] * w);
}

__global__ void bias_elu32_kernel(float* __restrict__ buf,
                                  const float* __restrict__ bias, int total) {
    int i = blockIdx.x * blockDim.x + threadIdx.x;
    if (i < total) {
        float v = buf[i] + bias[i & 31];
        buf[i] = elu1(v);
    }
}

// ---------------- GCN2: xw2 = act1 @ c2w (32->16), + self-loop init -------------
__global__ __launch_bounds__(256) void gcn_xw2_kernel(
    const float* __restrict__ g1, const float* __restrict__ W,  // 32x16
    const float* __restrict__ dinv,
    float* __restrict__ xw, float* __restrict__ outbuf) {
    __shared__ float sW[32 * 16];
    int tid = threadIdx.x;
    for (int i = tid; i < 32 * 16; i += 256) sW[i] = W[i];
    __syncthreads();
    int warp = tid >> 5, lane = tid & 31;
    int n = blockIdx.x * 8 + warp;
    if (n >= N_NODES) return;
    float r = g1[(size_t)n * 32 + lane];
    float accv = 0.f;
#pragma unroll
    for (int k = 0; k < 32; k++) {
        float a = __shfl_sync(0xffffffffu, r, k);
        if (lane < 16) accv += a * sW[k * 16 + lane];
    }
    if (lane < 16) {
        float di = dinv[n];
        xw[(size_t)n * 16 + lane] = accv;
        outbuf[(size_t)n * 16 + lane] = accv * di * di;
    }
}

__global__ void gcn_scatter16_kernel(const int* __restrict__ src,
                                     const int* __restrict__ dst,
                                     const float* __restrict__ dinv,
                                     const float* __restrict__ xw,
                                     float* __restrict__ outbuf, int E) {
    int idx = blockIdx.x * blockDim.x + threadIdx.x;
    int e = idx >> 4, c = idx & 15;
    if (e >= E) return;
    int s = src[e], d = dst[e];
    float w = dinv[s] * dinv[d];
    atomicAdd(&outbuf[(size_t)d * 16 + c], xw[(size_t)s * 16 + c] * w);
}

// ---------------- edge head -----------------------------------------------------
__global__ __launch_bounds__(256) void edge_head_kernel(
    const int* __restrict__ ei, const int* __restrict__ mask,
    const float* __restrict__ z, const float* __restrict__ c2b,
    const float* __restrict__ lw1, const float* __restrict__ lb1,
    const float* __restrict__ lw2, const float* __restrict__ lb2,
    float* __restrict__ out, int nsel, int E) {
    __shared__ float sW1[32 * 16], sB1[16], sW2[16 * 2], sB2[2], sCB[16];
    int tid = threadIdx.x;
    for (int i = tid; i < 512; i += 256) sW1[i] = lw1[i];
    if (tid < 16) { sB1[tid] = lb1[tid]; sCB[tid] = c2b[tid]; }
    if (tid < 32) sW2[tid] = lw2[tid];
    if (tid < 2)  sB2[tid] = lb2[tid];
    __syncthreads();
    int j = blockIdx.x * 256 + tid;
    if (j >= nsel) return;
    int idx = mask[j];
    int s = ei[idx], d = ei[E + idx];
    float e[32];
#pragma unroll
    for (int k = 0; k < 16; k++) e[k]      = z[(size_t)s * 16 + k] + sCB[k];
#pragma unroll
    for (int k = 0; k < 16; k++) e[16 + k] = z[(size_t)d * 16 + k] + sCB[k];
    float a1[16];
#pragma unroll
    for (int q = 0; q < 16; q++) {
        float accv = sB1[q];
#pragma unroll
        for (int k = 0; k < 32; k++) accv += e[k] * sW1[k * 16 + q];
        a1[q] = elu1(accv);
    }
    float o0 = sB2[0], o1 = sB2[1];
#pragma unroll
    for (int q = 0; q < 16; q++) {
        o0 += a1[q] * sW2[q * 2 + 0];
        o1 += a1[q] * sW2[q * 2 + 1];
    }
    out[(size_t)j * 2 + 0] = o0;
    out[(size_t)j * 2 + 1] = o1;
}

// ---------------- launch --------------------------------------------------------
extern "C" void kernel_launch(void* const* d_in, const int* in_sizes, int n_in,
                              void* d_out, int out_size) {
    const float* x    = (const float*)d_in[0];
    const int*   ei   = (const int*)d_in[1];
    const int*   mask = (const int*)d_in[2];
    const float* ln_g = (const float*)d_in[3];
    const float* ln_b = (const float*)d_in[4];
    const float* w0   = (const float*)d_in[5];
    const float* b0   = (const float*)d_in[6];
    const float* w1   = (const float*)d_in[7];
    const float* b1   = (const float*)d_in[8];
    const float* w2   = (const float*)d_in[9];
    const float* b2   = (const float*)d_in[10];
    const float* c1w  = (const float*)d_in[11];
    const float* c1b  = (const float*)d_in[12];
    const float* c2w  = (const float*)d_in[13];
    const float* c2b  = (const float*)d_in[14];
    const float* lw1  = (const float*)d_in[15];
    const float* lb1  = (const float*)d_in[16];
    const float* lw2  = (const float*)d_in[17];
    const float* lb2  = (const float*)d_in[18];

    int E    = in_sizes[1] / 2;
    int nsel = in_sizes[2];

    float *h, *h0, *h1, *h2, *xw1, *ac1, *xw2, *ac2, *dinv;
    cudaGetSymbolAddress((void**)&h,   g_h);
    cudaGetSymbolAddress((void**)&h0,  g_h0);
    cudaGetSymbolAddress((void**)&h1,  g_h1);
    cudaGetSymbolAddress((void**)&h2,  g_h2);
    cudaGetSymbolAddress((void**)&xw1, g_xw1);
    cudaGetSymbolAddress((void**)&ac1, g_ac1);
    cudaGetSymbolAddress((void**)&xw2, g_xw2);
    cudaGetSymbolAddress((void**)&ac2, g_ac2);
    cudaGetSymbolAddress((void**)&dinv, g_dinv);

    const int T = 256;
    // degrees
    deg_init_kernel<<<(N_NODES + T - 1) / T, T>>>(dinv);
    deg_accum_kernel<<<(E + T - 1) / T, T>>>(ei + E, dinv, E);
    deg_final_kernel<<<(N_NODES + T - 1) / T, T>>>(dinv);

    // maxpool + layernorm
    pool_ln_kernel<<<N_NODES, 256>>>(x, ln_g, ln_b, h);

    // MLP stack
    {
        dim3 grid((N_NODES + BM - 1) / BM, 512 / BN);
        sgemm_bias_act<<<grid, 256>>>(h, w0, b0, h0, N_NODES, 512, 1024, 1);
    }
    {
        dim3 grid((N_NODES + BM - 1) / BM, 128 / BN);
        sgemm_bias_act<<<grid, 256>>>(h0, w1, b1, h1, N_NODES, 128, 512, 1);
    }
    {
        dim3 grid((N_NODES + BM - 1) / BM, 64 / BN);
        sgemm_bias_act<<<grid, 256>>>(h1, w2, b2, h2, N_NODES, 64, 128, 1);
    }

    // GCN conv 1 (64->32)
    gcn_xw1_kernel<<<(N_NODES + 7) / 8, 256>>>(h2, c1w, dinv, xw1, ac1);
    {
        long long tot = (long long)E * 32;
        gcn_scatter32_kernel<<<(int)((tot + T - 1) / T), T>>>(ei, ei + E, dinv, xw1, ac1, E);
    }
    bias_elu32_kernel<<<(N_NODES * 32 + T - 1) / T, T>>>(ac1, c1b, N_NODES * 32);

    // GCN conv 2 (32->16)
    gcn_xw2_kernel<<<(N_NODES + 7) / 8, 256>>>(ac1, c2w, dinv, xw2, ac2);
    {
        long long tot = (long long)E * 16;
        gcn_scatter16_kernel<<<(int)((tot + T - 1) / T), T>>>(ei, ei + E, dinv, xw2, ac2, E);
    }

    // edge head
    edge_head_kernel<<<(nsel + 255) / 256, 256>>>(ei, mask, ac2, c2b, lw1, lb1, lw2,
                                                  lb2, (float*)d_out, nsel, E);
}